// round 7
// baseline (speedup 1.0000x reference)
#include <cuda_runtime.h>
#include <cuda_bf16.h>
#include <cstdint>

#define N_NODES   100000
#define N_EDGES   1600000
#define IN_FEATS  128
#define OUT_FEATS 64

#define SCAN_BLOCKS 98   // ceil(100000/1024)

// ---- scratch (__device__ globals; no allocs allowed) ----
__device__ float g_h[N_NODES * OUT_FEATS];      // projected features (25.6 MB)
__device__ int   g_counts[N_NODES];             // invariant: zero at launch entry/exit
__device__ int   g_offsets[N_NODES + 1];
__device__ int   g_cursor[N_NODES];
__device__ int   g_blockSums[SCAN_BLOCKS];
__device__ int2  g_sorted[N_EDGES];             // (src, bits(e)) sorted by dst

// ---------------------------------------------------------------------------
// Kernel 1: 8x8 register-tiled projection.
// Block 128 threads: tx = tid&7, ty = tid>>3. Tile: 128 nodes x 64 outs.
// Thread computes m = ty + i*16 (i<8), o = tx + j*8 (j<8).
// K in 4 chunks of 32, smem row stride 36 floats (16B aligned, conflict-free).
// Per 4-k step: 16 LDS.128 per 256 FMA -> LDS:FMA = 1:1 (balanced).
// ---------------------------------------------------------------------------
#define TM      128
#define KCHUNK  32
#define SP      36

__global__ __launch_bounds__(128) void proj_kernel(
    const float* __restrict__ feat,
    const float* __restrict__ W_w,   // [64][128]
    const float* __restrict__ W_b)   // [64]
{
    __shared__ float fS[TM * SP];        // 18432 B
    __shared__ float wS[OUT_FEATS * SP]; //  9216 B

    const int tid = threadIdx.x;
    const int tx  = tid & 7;
    const int ty  = tid >> 3;
    const int nodeBase = blockIdx.x * TM;

    float acc[8][8];
    #pragma unroll
    for (int i = 0; i < 8; i++)
        #pragma unroll
        for (int j = 0; j < 8; j++)
            acc[i][j] = 0.0f;

    for (int c = 0; c < 4; c++) {
        // stage chunk c: fS 128 rows x 8 float4, wS 64 rows x 8 float4
        #pragma unroll
        for (int it = 0; it < 8; it++) {
            int lin = tid + it * 128;      // 0..1023
            int r   = lin >> 3;
            int k4  = lin & 7;
            int gcol = c * KCHUNK + k4 * 4;
            int n = nodeBase + r;
            float4 fv = make_float4(0.f, 0.f, 0.f, 0.f);
            if (n < N_NODES)
                fv = *(const float4*)&feat[(size_t)n * IN_FEATS + gcol];
            *(float4*)&fS[r * SP + k4 * 4] = fv;
        }
        #pragma unroll
        for (int it = 0; it < 4; it++) {
            int lin = tid + it * 128;      // 0..511
            int r   = lin >> 3;
            int k4  = lin & 7;
            int gcol = c * KCHUNK + k4 * 4;
            float4 wv = *(const float4*)&W_w[(size_t)r * IN_FEATS + gcol];
            *(float4*)&wS[r * SP + k4 * 4] = wv;
        }
        __syncthreads();

        #pragma unroll
        for (int k = 0; k < KCHUNK; k += 4) {
            float4 a[8], b[8];
            #pragma unroll
            for (int i = 0; i < 8; i++)
                a[i] = *(const float4*)&fS[(ty + i * 16) * SP + k];
            #pragma unroll
            for (int j = 0; j < 8; j++)
                b[j] = *(const float4*)&wS[(tx + j * 8) * SP + k];
            #pragma unroll
            for (int i = 0; i < 8; i++)
                #pragma unroll
                for (int j = 0; j < 8; j++) {
                    acc[i][j] += a[i].x * b[j].x;
                    acc[i][j] += a[i].y * b[j].y;
                    acc[i][j] += a[i].z * b[j].z;
                    acc[i][j] += a[i].w * b[j].w;
                }
        }
        __syncthreads();
    }

    float bias[8];
    #pragma unroll
    for (int j = 0; j < 8; j++)
        bias[j] = __ldg(&W_b[tx + j * 8]);

    #pragma unroll
    for (int i = 0; i < 8; i++) {
        int n = nodeBase + ty + i * 16;
        if (n < N_NODES) {
            #pragma unroll
            for (int j = 0; j < 8; j++)
                g_h[(size_t)n * OUT_FEATS + tx + j * 8] = acc[i][j] + bias[j];
        }
    }
}

// ---------------------------------------------------------------------------
// CSR build: hist -> scan1 -> scan2 (fused cross-block) -> scatter.
// g_counts is zero on entry (BSS-zero first call; agg_kernel re-zeroes).
// ---------------------------------------------------------------------------
__global__ __launch_bounds__(1024) void hist_kernel(const int* __restrict__ dst)
{
    int i = blockIdx.x * 1024 + threadIdx.x;
    if (i < N_EDGES) atomicAdd(&g_counts[dst[i]], 1);
}

__global__ __launch_bounds__(1024) void scan1_kernel()
{
    __shared__ int s[1024];
    int i = blockIdx.x * 1024 + threadIdx.x;
    int v = (i < N_NODES) ? g_counts[i] : 0;
    s[threadIdx.x] = v;
    __syncthreads();
    #pragma unroll
    for (int d = 1; d < 1024; d <<= 1) {
        int t = (threadIdx.x >= d) ? s[threadIdx.x - d] : 0;
        __syncthreads();
        s[threadIdx.x] += t;
        __syncthreads();
    }
    if (i < N_NODES) g_offsets[i] = s[threadIdx.x] - v;   // block-local exclusive
    if (threadIdx.x == 1023) g_blockSums[blockIdx.x] = s[1023];
}

// Each block recomputes the prefix over 98 block sums itself (cheap), then
// applies it to its 1024 offsets and initializes the scatter cursor.
__global__ __launch_bounds__(1024) void scan2_kernel()
{
    __shared__ int bs[SCAN_BLOCKS];
    if (threadIdx.x < SCAN_BLOCKS) bs[threadIdx.x] = g_blockSums[threadIdx.x];
    __syncthreads();

    int prefix = 0;
    #pragma unroll 7
    for (int b = 0; b < SCAN_BLOCKS; b++)
        prefix += (b < blockIdx.x) ? bs[b] : 0;

    int i = blockIdx.x * 1024 + threadIdx.x;
    if (i < N_NODES) {
        int off = g_offsets[i] + prefix;
        g_offsets[i] = off;
        g_cursor[i]  = off;
    }
    if (blockIdx.x == 0 && threadIdx.x == 0)
        g_offsets[N_NODES] = N_EDGES;
}

__global__ __launch_bounds__(1024) void scatter_kernel(
    const int* __restrict__ src,
    const int* __restrict__ dst,
    const float* __restrict__ e)
{
    int i = blockIdx.x * 1024 + threadIdx.x;
    if (i >= N_EDGES) return;
    int d = dst[i];
    int p = atomicAdd(&g_cursor[d], 1);
    g_sorted[p] = make_int2(src[i], __float_as_int(e[i]));
}

// ---------------------------------------------------------------------------
// Aggregate: 16 lanes per node, lane c owns float4 chunk c.
// Register accumulation, fused ReLU, single write. Re-zeroes g_counts so the
// next replay's hist starts clean (deg comes from offsets, not counts).
// ---------------------------------------------------------------------------
__global__ __launch_bounds__(256) void agg_kernel(float* __restrict__ out)
{
    int t = blockIdx.x * 256 + threadIdx.x;
    int node = t >> 4;
    int c    = t & 15;
    if (node >= N_NODES) return;

    int beg = __ldg(&g_offsets[node]);
    int end = __ldg(&g_offsets[node + 1]);

    if (c == 0) g_counts[node] = 0;   // restore invariant for next replay

    const float4* h4 = (const float4*)g_h;
    float4 acc = make_float4(0.f, 0.f, 0.f, 0.f);

    int j = beg;
    for (; j + 2 <= end; j += 2) {
        int2 r0 = g_sorted[j];
        int2 r1 = g_sorted[j + 1];
        float4 h0 = h4[(size_t)r0.x * 16 + c];
        float4 h1 = h4[(size_t)r1.x * 16 + c];
        float w0 = __int_as_float(r0.y);
        float w1 = __int_as_float(r1.y);
        acc.x += h0.x * w0; acc.y += h0.y * w0;
        acc.z += h0.z * w0; acc.w += h0.w * w0;
        acc.x += h1.x * w1; acc.y += h1.y * w1;
        acc.z += h1.z * w1; acc.w += h1.w * w1;
    }
    if (j < end) {
        int2 r0 = g_sorted[j];
        float4 h0 = h4[(size_t)r0.x * 16 + c];
        float w0 = __int_as_float(r0.y);
        acc.x += h0.x * w0; acc.y += h0.y * w0;
        acc.z += h0.z * w0; acc.w += h0.w * w0;
    }

    acc.x = fmaxf(acc.x, 0.f);
    acc.y = fmaxf(acc.y, 0.f);
    acc.z = fmaxf(acc.z, 0.f);
    acc.w = fmaxf(acc.w, 0.f);
    ((float4*)out)[(size_t)node * 16 + c] = acc;
}

extern "C" void kernel_launch(void* const* d_in, const int* in_sizes, int n_in,
                              void* d_out, int out_size)
{
    const float* feat = (const float*)d_in[0];
    const int*   src  = (const int*)d_in[1];
    const int*   dst  = (const int*)d_in[2];
    const float* e    = (const float*)d_in[3];
    const float* W_w  = (const float*)d_in[4];
    const float* W_b  = (const float*)d_in[5];
    float* out = (float*)d_out;

    const int edgeBlocks = (N_EDGES + 1023) / 1024;   // 1563

    // CSR build (counts are zero on entry)
    hist_kernel<<<edgeBlocks, 1024>>>(dst);
    scan1_kernel<<<SCAN_BLOCKS, 1024>>>();
    scan2_kernel<<<SCAN_BLOCKS, 1024>>>();
    scatter_kernel<<<edgeBlocks, 1024>>>(src, dst, e);

    // Projection
    proj_kernel<<<(N_NODES + TM - 1) / TM, 128>>>(feat, W_w, W_b);

    // Aggregate + ReLU + write (+ counts reset)
    agg_kernel<<<(N_NODES * 16 + 255) / 256, 256>>>(out);
}